// round 2
// baseline (speedup 1.0000x reference)
#include <cuda_runtime.h>

#define BB 4
#define CC 256
#define NN 4096

// ---------------- scratch (allocation-free: __device__ globals) ----------------
__device__ float g_fmz [BB*CC*CC];     // fuse_mz  [b][c][d]
__device__ float g_yv  [BB*CC*NN];     // conv_value(y)
__device__ float g_fmzy[BB*CC*NN];     // fuse_mzy (= value, key input)
__device__ float g_v2  [BB*CC*NN];     // value_2
__device__ float g_q1  [BB*CC*NN];
__device__ float g_k1  [BB*CC*NN];
__device__ float g_q2  [BB*CC*NN];
__device__ float g_k2  [BB*CC*NN];
__device__ float g_os1 [BB*CC*NN];     // gamma * out_sim
__device__ float g_os2 [BB*CC*NN];     // gamma2 * out_sim_2
__device__ float g_H13 [BB*2*CC*NN];   // concat(H_1, H_3)
__device__ float g_Htra[BB*2*CC*NN];
__device__ float g_H5  [BB*CC*NN];     // pre-sigmoid
__device__ float g_H6  [BB*CC*NN];     // pre-sigmoid

// ---------------- tiny prep: mv, m_line_t, zv, fuse_mz ----------------
// grid (8, BB): blockIdx.y = batch, blockIdx.x = 32-row slice of fuse_mz
__global__ void prep_kernel(const float* __restrict__ Wv, const float* __restrict__ z,
                            const float* __restrict__ m_,  const float* __restrict__ Wfc,
                            const float* __restrict__ bfc, float* __restrict__ fmz)
{
    __shared__ float s_mlt[36*256];   // m_line_t [j][d]
    __shared__ float s_tmp[256*9];    // mv [c][k], later reused for zv slice [32][36]
    const int b  = blockIdx.y;
    const int c0 = blockIdx.x * 32;
    const int tid = threadIdx.x;

    // mv[c][k] = sum_i Wv[c][i] * m[b][i][k]
    for (int idx = tid; idx < 256*9; idx += 256) {
        int c = idx / 9, k = idx % 9;
        const float* wr = Wv + c*256;
        const float* mr = m_ + (long)(b*256)*9 + k;
        float s = 0.f;
        for (int i = 0; i < 256; i++) s += wr[i] * mr[i*9];
        s_tmp[idx] = s;
    }
    __syncthreads();
    // m_line_t[j][d] = bfc[j] + sum_k mv[d][k] * Wfc[j][k]
    for (int idx = tid; idx < 36*256; idx += 256) {
        int j = idx >> 8, d = idx & 255;
        float s = bfc[j];
        for (int k = 0; k < 9; k++) s += s_tmp[d*9+k] * Wfc[j*9+k];
        s_mlt[idx] = s;
    }
    __syncthreads();
    // zv slice [32][36]: zv[c][j] = sum_i Wv[c][i] * z[b][i][j]
    for (int idx = tid; idx < 32*36; idx += 256) {
        int cl = idx / 36, j = idx % 36;
        const float* wr = Wv + (c0+cl)*256;
        const float* zr = z + (long)(b*256)*36 + j;
        float s = 0.f;
        for (int i = 0; i < 256; i++) s += wr[i] * zr[i*36];
        s_tmp[idx] = s;
    }
    __syncthreads();
    // fuse_mz[c][d] = sum_j zv[c][j] * m_line_t[j][d]
    for (int idx = tid; idx < 32*256; idx += 256) {
        int cl = idx >> 8, d = idx & 255;
        float s = 0.f;
        for (int j = 0; j < 36; j++) s += s_tmp[cl*36+j] * s_mlt[j*256+d];
        fmz[((long)(b*256) + c0 + cl)*256 + d] = s;
    }
}

// ---------------- generic batched SGEMM: Out[b] = W(+b?) @ In[b] (+bias)(+Add) ----------------
// 128x128 tile, BK=8, 256 threads, 8x8 register micro-tile, register double-buffered
// global loads. M%128==0, N%128==0, K%8==0.
__global__ __launch_bounds__(256)
void sgemm128(const float* __restrict__ W, long wBS,
              const float* __restrict__ In, long inBS,
              const float* __restrict__ bias,
              const float* __restrict__ Add, long addBS,
              float* __restrict__ Out, long outBS,
              int M, int N, int K)
{
    __shared__ float As[8][128];
    __shared__ float Bs[8][128];
    const int b = blockIdx.z;
    W   += (long)b * wBS;
    In  += (long)b * inBS;
    Out += (long)b * outBS;
    const float* AddB = Add ? (Add + (long)b * addBS) : (const float*)0;

    const int n0 = blockIdx.x * 128;
    const int m0 = blockIdx.y * 128;
    const int tid = threadIdx.x;
    const int tx = tid & 15, ty = tid >> 4;

    float acc[8][8];
    #pragma unroll
    for (int i = 0; i < 8; i++)
        #pragma unroll
        for (int j = 0; j < 8; j++) acc[i][j] = 0.f;

    const int mmL = tid >> 1;
    const int kqL = (tid & 1) * 4;
    const int kkL = tid >> 5;
    const int nnL = (tid & 31) * 4;

    // prefetch first slab into registers
    float4 aReg = *(const float4*)&W[(long)(m0+mmL)*K + kqL];
    float4 bReg = *(const float4*)&In[(long)kkL*N + n0 + nnL];

    for (int k0 = 0; k0 < K; k0 += 8) {
        As[kqL+0][mmL] = aReg.x; As[kqL+1][mmL] = aReg.y;
        As[kqL+2][mmL] = aReg.z; As[kqL+3][mmL] = aReg.w;
        *(float4*)&Bs[kkL][nnL] = bReg;
        __syncthreads();
        if (k0 + 8 < K) {   // prefetch next slab; overlaps with FMAs below
            aReg = *(const float4*)&W[(long)(m0+mmL)*K + k0 + 8 + kqL];
            bReg = *(const float4*)&In[(long)(k0+8+kkL)*N + n0 + nnL];
        }
        #pragma unroll
        for (int kk = 0; kk < 8; kk++) {
            float4 a0 = *(float4*)&As[kk][ty*8];
            float4 a1 = *(float4*)&As[kk][ty*8+4];
            float4 b0 = *(float4*)&Bs[kk][tx*8];
            float4 b1 = *(float4*)&Bs[kk][tx*8+4];
            float av[8] = {a0.x,a0.y,a0.z,a0.w,a1.x,a1.y,a1.z,a1.w};
            float bv[8] = {b0.x,b0.y,b0.z,b0.w,b1.x,b1.y,b1.z,b1.w};
            #pragma unroll
            for (int i = 0; i < 8; i++)
                #pragma unroll
                for (int j = 0; j < 8; j++)
                    acc[i][j] += av[i]*bv[j];
        }
        __syncthreads();
    }
    #pragma unroll
    for (int i = 0; i < 8; i++) {
        const int mrow = m0 + ty*8 + i;
        const float bi = bias ? bias[mrow] : 0.f;
        #pragma unroll
        for (int j = 0; j < 8; j++) {
            const int ncol = n0 + tx*8 + j;
            float v = acc[i][j] + bi;
            if (AddB) v += AddB[(long)mrow*N + ncol];
            Out[(long)mrow*N + ncol] = v;
        }
    }
}

// ---------------- streaming attention (no-max softmax; logits are tiny) ----------------
// out[c,n] = gamma * (sum_m exp(q_n . k_m) * V[c,m]) / (sum_m exp(q_n . k_m))
// grid (NN/64, BB), 256 threads. Block = 64 queries, loops 64-key tiles.
__global__ __launch_bounds__(256)
void attn_kernel(const float* __restrict__ Q, const float* __restrict__ Kp,
                 const float* __restrict__ V, const float* __restrict__ gamma,
                 float* __restrict__ Out)
{
    __shared__ float Qs[32][64];
    __shared__ float Ks[32][64];
    __shared__ float Ps[64][64];
    __shared__ float Vs[16][256];
    __shared__ float denom[64];

    const int b  = blockIdx.y;
    const int q0 = blockIdx.x * 64;
    const long base = (long)b * CC * NN;
    Q += base; Kp += base; V += base; Out += base;

    const int tid = threadIdx.x;
    const int tx  = tid & 15, ty  = tid >> 4;   // phase-1 map (16x16): 4q x 4k
    const int tx2 = tid & 31, ty2 = tid >> 5;   // phase-2 map (8x32): 8q x 8c

    float acc[8][8];
    #pragma unroll
    for (int i = 0; i < 8; i++)
        #pragma unroll
        for (int j = 0; j < 8; j++) acc[i][j] = 0.f;
    float dpart[4] = {0.f, 0.f, 0.f, 0.f};
    if (tid < 64) denom[tid] = 0.f;

    const int rL   = tid >> 4;           // 0..15
    const int colL = (tid & 15) * 4;     // 0..60

    for (int kt = 0; kt < NN/64; kt++) {
        const int k0 = kt * 64;
        float S[4][4] = {};
        // phase 1: S[64q][64k] = Q^T K over c=256, 32-row smem chunks
        for (int c0 = 0; c0 < CC; c0 += 32) {
            *(float4*)&Qs[rL   ][colL] = *(const float4*)&Q [(long)(c0+rL   )*NN + q0 + colL];
            *(float4*)&Qs[rL+16][colL] = *(const float4*)&Q [(long)(c0+rL+16)*NN + q0 + colL];
            *(float4*)&Ks[rL   ][colL] = *(const float4*)&Kp[(long)(c0+rL   )*NN + k0 + colL];
            *(float4*)&Ks[rL+16][colL] = *(const float4*)&Kp[(long)(c0+rL+16)*NN + k0 + colL];
            __syncthreads();
            #pragma unroll
            for (int i = 0; i < 32; i++) {
                float4 qa = *(float4*)&Qs[i][ty*4];
                float4 kb = *(float4*)&Ks[i][tx*4];
                float qv[4] = {qa.x,qa.y,qa.z,qa.w};
                float kv[4] = {kb.x,kb.y,kb.z,kb.w};
                #pragma unroll
                for (int qi = 0; qi < 4; qi++)
                    #pragma unroll
                    for (int ki = 0; ki < 4; ki++)
                        S[qi][ki] += qv[qi]*kv[ki];
            }
            __syncthreads();
        }
        // exp -> Ps, denominator partials
        #pragma unroll
        for (int qi = 0; qi < 4; qi++)
            #pragma unroll
            for (int ki = 0; ki < 4; ki++) {
                float p = __expf(S[qi][ki]);
                dpart[qi] += p;
                Ps[ty*4+qi][tx*4+ki] = p;
            }
        __syncthreads();
        // phase 2: acc[q][c] += P[q][m] * V[c][m], m in 4 chunks of 16
        #pragma unroll
        for (int mc = 0; mc < 4; mc++) {
            const float4* vp = (const float4*)&V[(long)tid*NN + k0 + mc*16];
            float4 v0 = vp[0], v1 = vp[1], v2 = vp[2], v3 = vp[3];
            Vs[ 0][tid]=v0.x; Vs[ 1][tid]=v0.y; Vs[ 2][tid]=v0.z; Vs[ 3][tid]=v0.w;
            Vs[ 4][tid]=v1.x; Vs[ 5][tid]=v1.y; Vs[ 6][tid]=v1.z; Vs[ 7][tid]=v1.w;
            Vs[ 8][tid]=v2.x; Vs[ 9][tid]=v2.y; Vs[10][tid]=v2.z; Vs[11][tid]=v2.w;
            Vs[12][tid]=v3.x; Vs[13][tid]=v3.y; Vs[14][tid]=v3.z; Vs[15][tid]=v3.w;
            __syncthreads();
            #pragma unroll
            for (int mm = 0; mm < 16; mm++) {
                float pv[8], vv[8];
                #pragma unroll
                for (int qi = 0; qi < 8; qi++) pv[qi] = Ps[ty2*8+qi][mc*16+mm];
                #pragma unroll
                for (int ci = 0; ci < 8; ci++) vv[ci] = Vs[mm][ci*32+tx2];
                #pragma unroll
                for (int qi = 0; qi < 8; qi++)
                    #pragma unroll
                    for (int ci = 0; ci < 8; ci++)
                        acc[qi][ci] += pv[qi]*vv[ci];
            }
            __syncthreads();
        }
    }
    #pragma unroll
    for (int qi = 0; qi < 4; qi++) atomicAdd(&denom[ty*4+qi], dpart[qi]);
    __syncthreads();
    const float g = gamma[0];
    #pragma unroll
    for (int qi = 0; qi < 8; qi++) {
        const float inv = g / denom[ty2*8+qi];
        #pragma unroll
        for (int ci = 0; ci < 8; ci++)
            Out[(long)(ci*32+tx2)*NN + q0 + ty2*8 + qi] = acc[qi][ci] * inv;
    }
}

// ---------------- epilogue: sigmoid -> 2-way softmax -> blend + residual ----------------
__global__ void final_kernel(const float* __restrict__ x,  const float* __restrict__ h5,
                             const float* __restrict__ h6, const float* __restrict__ o1,
                             const float* __restrict__ o2, float* __restrict__ out, int n)
{
    int i = blockIdx.x*blockDim.x + threadIdx.x;
    const int stride = gridDim.x*blockDim.x;
    for (; i < n; i += stride) {
        float s5 = 1.f/(1.f+__expf(-h5[i]));
        float s6 = 1.f/(1.f+__expf(-h6[i]));
        float e5 = __expf(s5), e6 = __expf(s6);
        float w = e5/(e5+e6);
        out[i] = w*o1[i] + (1.f-w)*o2[i] + x[i];
    }
}

// ---------------- host ----------------
static inline void gemm_launch(const float* W, long wBS, const float* In, long inBS,
                               const float* bias, const float* Add, long addBS,
                               float* Out, long outBS, int M, int N, int K)
{
    dim3 grid(N/128, M/128, BB);
    sgemm128<<<grid, 256>>>(W, wBS, In, inBS, bias, Add, addBS, Out, outBS, M, N, K);
}

extern "C" void kernel_launch(void* const* d_in, const int* in_sizes, int n_in,
                              void* d_out, int out_size)
{
    (void)in_sizes; (void)n_in; (void)out_size;
    const float* x    = (const float*)d_in[0];
    const float* y    = (const float*)d_in[1];
    const float* z    = (const float*)d_in[2];
    const float* m    = (const float*)d_in[3];
    const float* Wv   = (const float*)d_in[4];
    const float* Wv2  = (const float*)d_in[5];
    const float* Wq   = (const float*)d_in[6];
    const float* bq   = (const float*)d_in[7];
    const float* Wk   = (const float*)d_in[8];
    const float* bk   = (const float*)d_in[9];
    const float* Wq2  = (const float*)d_in[10];
    const float* bq2  = (const float*)d_in[11];
    const float* Wk2  = (const float*)d_in[12];
    const float* bk2  = (const float*)d_in[13];
    const float* Win1 = (const float*)d_in[14];
    const float* bin1 = (const float*)d_in[15];
    const float* Win3 = (const float*)d_in[16];
    const float* bin3 = (const float*)d_in[17];
    const float* Wtr  = (const float*)d_in[18];
    const float* btr  = (const float*)d_in[19];
    const float* Wout2= (const float*)d_in[20];
    const float* bout2= (const float*)d_in[21];
    const float* Wout3= (const float*)d_in[22];
    const float* bout3= (const float*)d_in[23];
    const float* Wfc  = (const float*)d_in[24];
    const float* bfc  = (const float*)d_in[25];
    const float* gamma  = (const float*)d_in[26];
    const float* gamma2 = (const float*)d_in[27];
    float* out = (float*)d_out;

    float *fmz, *yv, *fmzy, *v2, *q1, *k1, *q2, *k2, *os1, *os2, *H13, *Htra, *H5, *H6;
    cudaGetSymbolAddress((void**)&fmz,  g_fmz);
    cudaGetSymbolAddress((void**)&yv,   g_yv);
    cudaGetSymbolAddress((void**)&fmzy, g_fmzy);
    cudaGetSymbolAddress((void**)&v2,   g_v2);
    cudaGetSymbolAddress((void**)&q1,   g_q1);
    cudaGetSymbolAddress((void**)&k1,   g_k1);
    cudaGetSymbolAddress((void**)&q2,   g_q2);
    cudaGetSymbolAddress((void**)&k2,   g_k2);
    cudaGetSymbolAddress((void**)&os1,  g_os1);
    cudaGetSymbolAddress((void**)&os2,  g_os2);
    cudaGetSymbolAddress((void**)&H13,  g_H13);
    cudaGetSymbolAddress((void**)&Htra, g_Htra);
    cudaGetSymbolAddress((void**)&H5,   g_H5);
    cudaGetSymbolAddress((void**)&H6,   g_H6);

    const long CN = (long)CC*NN;

    // tiny prep path (fuse_mz) and yv GEMM
    prep_kernel<<<dim3(8, BB), 256>>>(Wv, z, m, Wfc, bfc, fmz);
    gemm_launch(Wv, 0, y, CN, 0, 0, 0, yv, CN, CC, NN, CC);
    // fuse_mzy = fuse_mz[b] @ yv[b] + yv[b]   (batched W)
    gemm_launch(fmz, (long)CC*CC, yv, CN, 0, yv, CN, fmzy, CN, CC, NN, CC);
    // projections
    gemm_launch(Wv2, 0, x,    CN, 0,   0, 0, v2, CN, CC, NN, CC);
    gemm_launch(Wq,  0, x,    CN, bq,  0, 0, q1, CN, CC, NN, CC);
    gemm_launch(Wk,  0, fmzy, CN, bk,  0, 0, k1, CN, CC, NN, CC);
    gemm_launch(Wq2, 0, x,    CN, bq2, 0, 0, q2, CN, CC, NN, CC);
    gemm_launch(Wk2, 0, x,    CN, bk2, 0, 0, k2, CN, CC, NN, CC);
    // two attention branches (gamma folded in)
    attn_kernel<<<dim3(NN/64, BB), 256>>>(q1, k1, fmzy, gamma,  os1);
    attn_kernel<<<dim3(NN/64, BB), 256>>>(q2, k2, v2,   gamma2, os2);
    // gated fusion path
    gemm_launch(Win1, 0, os1, CN, bin1, 0, 0, H13,          2*CN, CC,   NN, CC);
    gemm_launch(Win3, 0, os2, CN, bin3, 0, 0, H13 + CN,     2*CN, CC,   NN, CC);
    gemm_launch(Wtr,  0, H13, 2*CN, btr, 0, 0, Htra,        2*CN, 2*CC, NN, 2*CC);
    gemm_launch(Wout2,0, Htra,      2*CN, bout2, 0, 0, H5,  CN, CC, NN, CC);
    gemm_launch(Wout3,0, Htra + CN, 2*CN, bout3, 0, 0, H6,  CN, CC, NN, CC);
    // epilogue
    final_kernel<<<2048, 256>>>(x, H5, H6, os1, os2, out, BB*CC*NN);
}

// round 4
// speedup vs baseline: 1.0934x; 1.0934x over previous
#include <cuda_runtime.h>

#define BB 4
#define CC 256
#define NN 4096

typedef unsigned long long ull;

// ---------------- f32x2 helpers (SASS FFMA2 path, PTX-only) ----------------
__device__ __forceinline__ ull pk2f(float a, float b) {
    ull r; asm("mov.b64 %0, {%1, %2};" : "=l"(r) : "f"(a), "f"(b)); return r;
}
__device__ __forceinline__ ull dup2f(float a) { return pk2f(a, a); }
__device__ __forceinline__ ull f2fma(ull a, ull b, ull c) {
    ull d; asm("fma.rn.f32x2 %0, %1, %2, %3;" : "=l"(d) : "l"(a), "l"(b), "l"(c)); return d;
}
__device__ __forceinline__ float2 upk2f(ull v) {
    float2 f; asm("mov.b64 {%0, %1}, %2;" : "=f"(f.x), "=f"(f.y) : "l"(v)); return f;
}

// ---------------- scratch (allocation-free: __device__ globals) ----------------
__device__ float g_fmz [BB*CC*CC];
__device__ float g_yv  [BB*CC*NN];
__device__ float g_fmzy[BB*CC*NN];
__device__ float g_v2  [BB*CC*NN];
__device__ float g_q1  [BB*CC*NN];
__device__ float g_k1  [BB*CC*NN];
__device__ float g_q2  [BB*CC*NN];
__device__ float g_k2  [BB*CC*NN];
__device__ float g_vt1 [BB*NN*CC];   // fmzy transposed [b][n][c]
__device__ float g_vt2 [BB*NN*CC];   // v2 transposed
__device__ float g_os1 [BB*CC*NN];
__device__ float g_os2 [BB*CC*NN];
__device__ float g_H13 [BB*2*CC*NN];
__device__ float g_Htra[BB*2*CC*NN];
__device__ float g_H5  [BB*CC*NN];
__device__ float g_H6  [BB*CC*NN];

// ---------------- tiny prep: mv, m_line_t, zv, fuse_mz ----------------
__global__ void prep_kernel(const float* __restrict__ Wv, const float* __restrict__ z,
                            const float* __restrict__ m_,  const float* __restrict__ Wfc,
                            const float* __restrict__ bfc, float* __restrict__ fmz)
{
    __shared__ float s_mlt[36*256];
    __shared__ float s_tmp[256*9];
    const int b  = blockIdx.y;
    const int c0 = blockIdx.x * 32;
    const int tid = threadIdx.x;

    for (int idx = tid; idx < 256*9; idx += 256) {
        int c = idx / 9, k = idx % 9;
        const float* wr = Wv + c*256;
        const float* mr = m_ + (long)(b*256)*9 + k;
        float s = 0.f;
        for (int i = 0; i < 256; i++) s += wr[i] * mr[i*9];
        s_tmp[idx] = s;
    }
    __syncthreads();
    for (int idx = tid; idx < 36*256; idx += 256) {
        int j = idx >> 8, d = idx & 255;
        float s = bfc[j];
        for (int k = 0; k < 9; k++) s += s_tmp[d*9+k] * Wfc[j*9+k];
        s_mlt[idx] = s;
    }
    __syncthreads();
    for (int idx = tid; idx < 32*36; idx += 256) {
        int cl = idx / 36, j = idx % 36;
        const float* wr = Wv + (c0+cl)*256;
        const float* zr = z + (long)(b*256)*36 + j;
        float s = 0.f;
        for (int i = 0; i < 256; i++) s += wr[i] * zr[i*36];
        s_tmp[idx] = s;
    }
    __syncthreads();
    for (int idx = tid; idx < 32*256; idx += 256) {
        int cl = idx >> 8, d = idx & 255;
        float s = 0.f;
        for (int j = 0; j < 36; j++) s += s_tmp[cl*36+j] * s_mlt[j*256+d];
        fmz[((long)(b*256) + c0 + cl)*256 + d] = s;
    }
}

// ---------------- transpose [C][N] -> [N][C] per batch ----------------
__global__ __launch_bounds__(256)
void transpose_kernel(const float* __restrict__ A, float* __restrict__ At)
{
    __shared__ float t[32][33];
    const int b = blockIdx.z;
    const float* Ab = A + (long)b*CC*NN;
    float* Atb = At + (long)b*NN*CC;
    const int n0 = blockIdx.x*32, c0 = blockIdx.y*32;
    const int tx = threadIdx.x, ty = threadIdx.y;
    #pragma unroll
    for (int j = 0; j < 4; j++)
        t[ty+j*8][tx] = Ab[(long)(c0+ty+j*8)*NN + n0 + tx];
    __syncthreads();
    #pragma unroll
    for (int j = 0; j < 4; j++)
        Atb[(long)(n0+ty+j*8)*CC + c0 + tx] = t[tx][ty+j*8];
}

// ---------------- generic batched SGEMM (f32x2 inner) ----------------
__global__ __launch_bounds__(256)
void sgemm128(const float* __restrict__ W, long wBS,
              const float* __restrict__ In, long inBS,
              const float* __restrict__ bias,
              const float* __restrict__ Add, long addBS,
              float* __restrict__ Out, long outBS,
              int M, int N, int K)
{
    __shared__ float As[8][128];
    __shared__ float Bs[8][128];
    const int b = blockIdx.z;
    W   += (long)b * wBS;
    In  += (long)b * inBS;
    Out += (long)b * outBS;
    const float* AddB = Add ? (Add + (long)b * addBS) : (const float*)0;

    const int n0 = blockIdx.x * 128;
    const int m0 = blockIdx.y * 128;
    const int tid = threadIdx.x;
    const int tx = tid & 15, ty = tid >> 4;

    ull acc2[8][4];
    #pragma unroll
    for (int i = 0; i < 8; i++)
        #pragma unroll
        for (int j = 0; j < 4; j++) acc2[i][j] = 0ull;

    const int mmL = tid >> 1;
    const int kqL = (tid & 1) * 4;
    const int kkL = tid >> 5;
    const int nnL = (tid & 31) * 4;

    float4 aReg = *(const float4*)&W[(long)(m0+mmL)*K + kqL];
    float4 bReg = *(const float4*)&In[(long)kkL*N + n0 + nnL];

    for (int k0 = 0; k0 < K; k0 += 8) {
        As[kqL+0][mmL] = aReg.x; As[kqL+1][mmL] = aReg.y;
        As[kqL+2][mmL] = aReg.z; As[kqL+3][mmL] = aReg.w;
        *(float4*)&Bs[kkL][nnL] = bReg;
        __syncthreads();
        if (k0 + 8 < K) {
            aReg = *(const float4*)&W[(long)(m0+mmL)*K + k0 + 8 + kqL];
            bReg = *(const float4*)&In[(long)(k0+8+kkL)*N + n0 + nnL];
        }
        #pragma unroll
        for (int kk = 0; kk < 8; kk++) {
            float4 a0 = *(float4*)&As[kk][ty*8];
            float4 a1 = *(float4*)&As[kk][ty*8+4];
            float4 b0 = *(float4*)&Bs[kk][tx*8];
            float4 b1 = *(float4*)&Bs[kk][tx*8+4];
            ull bp0 = pk2f(b0.x,b0.y), bp1 = pk2f(b0.z,b0.w);
            ull bp2 = pk2f(b1.x,b1.y), bp3 = pk2f(b1.z,b1.w);
            float av[8] = {a0.x,a0.y,a0.z,a0.w,a1.x,a1.y,a1.z,a1.w};
            #pragma unroll
            for (int i = 0; i < 8; i++) {
                ull ad = dup2f(av[i]);
                acc2[i][0] = f2fma(ad, bp0, acc2[i][0]);
                acc2[i][1] = f2fma(ad, bp1, acc2[i][1]);
                acc2[i][2] = f2fma(ad, bp2, acc2[i][2]);
                acc2[i][3] = f2fma(ad, bp3, acc2[i][3]);
            }
        }
        __syncthreads();
    }
    #pragma unroll
    for (int i = 0; i < 8; i++) {
        const int mrow = m0 + ty*8 + i;
        const float bi = bias ? bias[mrow] : 0.f;
        #pragma unroll
        for (int jp = 0; jp < 4; jp++) {
            const int ncol = n0 + tx*8 + jp*2;
            float2 v = upk2f(acc2[i][jp]);
            v.x += bi; v.y += bi;
            if (AddB) {
                float2 ad = *(const float2*)&AddB[(long)mrow*N + ncol];
                v.x += ad.x; v.y += ad.y;
            }
            *(float2*)&Out[(long)mrow*N + ncol] = v;
        }
    }
}

// ---------------- streaming attention (both branches), f32x2 ----------------
// Block: 64 queries. Key tiles of 128. Per-thread: 8q x 4k logits, 8q x 8c output.
// Requires V transposed to [N][C]. grid (NN/64, BB, 2), 256 threads.
__global__ __launch_bounds__(256)
void attn_kernel(const float* __restrict__ Q1, const float* __restrict__ K1,
                 const float* __restrict__ Vt1, const float* __restrict__ g1p, float* __restrict__ O1,
                 const float* __restrict__ Q2, const float* __restrict__ K2,
                 const float* __restrict__ Vt2, const float* __restrict__ g2p, float* __restrict__ O2)
{
    __shared__ float pool[10304];
    // phase1: Qs = pool[0..2047] as [32][64]; Ks = pool[2048..6143] as [32][128]
    // after:  Ps = pool[0..8191] as [64][128]
    float* Ps = pool;
    float* Vs = pool + 8192;       // [8][256]
    float* denom = pool + 10240;   // [64]

    const int br = blockIdx.z;
    const float* Q  = br ? Q2  : Q1;
    const float* Kp = br ? K2  : K1;
    const float* Vt = br ? Vt2 : Vt1;
    const float* gp = br ? g2p : g1p;
    float* Out      = br ? O2  : O1;

    const int b  = blockIdx.y;
    const int q0 = blockIdx.x * 64;
    Q  += (long)b*CC*NN;
    Kp += (long)b*CC*NN;
    Vt += (long)b*NN*CC;
    Out+= (long)b*CC*NN;

    const int tid = threadIdx.x;
    const int tx = tid & 31;        // k-group (phase1) / c-lane (phase2)
    const int ty = tid >> 5;        // q-group (8 queries each)
    const int lr = tid >> 3;        // loader row 0..31
    const int lq = (tid & 7) * 8;
    const int lk = (tid & 7) * 16;

    if (tid < 64) denom[tid] = 0.f;

    ull acc2[8][4];
    #pragma unroll
    for (int i = 0; i < 8; i++)
        #pragma unroll
        for (int j = 0; j < 4; j++) acc2[i][j] = 0ull;
    float dpart[8] = {0.f,0.f,0.f,0.f,0.f,0.f,0.f,0.f};

    for (int kt = 0; kt < NN/128; kt++) {
        const int k0 = kt * 128;
        ull S2[8][2];
        #pragma unroll
        for (int i = 0; i < 8; i++) { S2[i][0] = 0ull; S2[i][1] = 0ull; }

        // ---- phase 1: S[64q][128k] over C=256 in 32-row chunks ----
        for (int c0 = 0; c0 < CC; c0 += 32) {
            __syncthreads();   // previous consumers of pool done
            *(float4*)&pool[lr*64 + lq]     = *(const float4*)&Q [(long)(c0+lr)*NN + q0 + lq];
            *(float4*)&pool[lr*64 + lq + 4] = *(const float4*)&Q [(long)(c0+lr)*NN + q0 + lq + 4];
            #pragma unroll
            for (int j = 0; j < 4; j++)
                *(float4*)&pool[2048 + lr*128 + lk + j*4] =
                    *(const float4*)&Kp[(long)(c0+lr)*NN + k0 + lk + j*4];
            __syncthreads();
            #pragma unroll 8
            for (int i = 0; i < 32; i++) {
                float4 qa = *(float4*)&pool[i*64 + ty*8];
                float4 qb = *(float4*)&pool[i*64 + ty*8 + 4];
                float4 kb = *(float4*)&pool[2048 + i*128 + tx*4];
                ull kp0 = pk2f(kb.x, kb.y), kp1 = pk2f(kb.z, kb.w);
                ull d;
                d = dup2f(qa.x); S2[0][0]=f2fma(d,kp0,S2[0][0]); S2[0][1]=f2fma(d,kp1,S2[0][1]);
                d = dup2f(qa.y); S2[1][0]=f2fma(d,kp0,S2[1][0]); S2[1][1]=f2fma(d,kp1,S2[1][1]);
                d = dup2f(qa.z); S2[2][0]=f2fma(d,kp0,S2[2][0]); S2[2][1]=f2fma(d,kp1,S2[2][1]);
                d = dup2f(qa.w); S2[3][0]=f2fma(d,kp0,S2[3][0]); S2[3][1]=f2fma(d,kp1,S2[3][1]);
                d = dup2f(qb.x); S2[4][0]=f2fma(d,kp0,S2[4][0]); S2[4][1]=f2fma(d,kp1,S2[4][1]);
                d = dup2f(qb.y); S2[5][0]=f2fma(d,kp0,S2[5][0]); S2[5][1]=f2fma(d,kp1,S2[5][1]);
                d = dup2f(qb.z); S2[6][0]=f2fma(d,kp0,S2[6][0]); S2[6][1]=f2fma(d,kp1,S2[6][1]);
                d = dup2f(qb.w); S2[7][0]=f2fma(d,kp0,S2[7][0]); S2[7][1]=f2fma(d,kp1,S2[7][1]);
            }
        }
        __syncthreads();
        // ---- exp -> Ps (overlays Qs/Ks), denominator partials ----
        #pragma unroll
        for (int qi = 0; qi < 8; qi++) {
            float2 s0 = upk2f(S2[qi][0]);
            float2 s1 = upk2f(S2[qi][1]);
            float p0 = __expf(s0.x), p1 = __expf(s0.y);
            float p2 = __expf(s1.x), p3 = __expf(s1.y);
            dpart[qi] += (p0+p1) + (p2+p3);
            float4 w; w.x=p0; w.y=p1; w.z=p2; w.w=p3;
            *(float4*)&Ps[(ty*8+qi)*128 + tx*4] = w;
        }
        __syncthreads();
        // ---- phase 2: acc[q][c] += P[q][m] * Vt[m][c], m chunks of 8 ----
        for (int mc = 0; mc < 16; mc++) {
            {
                const int r  = tid >> 5;
                const int cc = (tid & 31) * 8;
                const float* src = &Vt[(long)(k0 + mc*8 + r)*CC + cc];
                *(float4*)&Vs[r*256 + cc]     = *(const float4*)src;
                *(float4*)&Vs[r*256 + cc + 4] = *(const float4*)(src + 4);
            }
            __syncthreads();
            #pragma unroll
            for (int mm = 0; mm < 8; mm++) {
                ull vv0 = *(const ull*)&Vs[mm*256 +   0 + tx*2];
                ull vv1 = *(const ull*)&Vs[mm*256 +  64 + tx*2];
                ull vv2 = *(const ull*)&Vs[mm*256 + 128 + tx*2];
                ull vv3 = *(const ull*)&Vs[mm*256 + 192 + tx*2];
                #pragma unroll
                for (int qi = 0; qi < 8; qi++) {
                    ull pd = dup2f(Ps[(ty*8+qi)*128 + mc*8 + mm]);
                    acc2[qi][0] = f2fma(pd, vv0, acc2[qi][0]);
                    acc2[qi][1] = f2fma(pd, vv1, acc2[qi][1]);
                    acc2[qi][2] = f2fma(pd, vv2, acc2[qi][2]);
                    acc2[qi][3] = f2fma(pd, vv3, acc2[qi][3]);
                }
            }
            __syncthreads();
        }
    }

    #pragma unroll
    for (int qi = 0; qi < 8; qi++) atomicAdd(&denom[ty*8+qi], dpart[qi]);
    __syncthreads();

    const float g = gp[0];
    float inv[8];
    #pragma unroll
    for (int qi = 0; qi < 8; qi++) inv[qi] = g / denom[ty*8+qi];
    const int nb = q0 + ty*8;
    #pragma unroll
    for (int gg = 0; gg < 4; gg++) {
        const long c = gg*64 + tx*2;
        #pragma unroll
        for (int qp = 0; qp < 4; qp++) {
            float2 e = upk2f(acc2[2*qp][gg]);
            float2 o = upk2f(acc2[2*qp+1][gg]);
            *(float2*)&Out[c*NN + nb + 2*qp]     = make_float2(e.x*inv[2*qp], o.x*inv[2*qp+1]);
            *(float2*)&Out[(c+1)*NN + nb + 2*qp] = make_float2(e.y*inv[2*qp], o.y*inv[2*qp+1]);
        }
    }
}

// ---------------- epilogue ----------------
__global__ void final_kernel(const float* __restrict__ x,  const float* __restrict__ h5,
                             const float* __restrict__ h6, const float* __restrict__ o1,
                             const float* __restrict__ o2, float* __restrict__ out, int n)
{
    int i = blockIdx.x*blockDim.x + threadIdx.x;
    const int stride = gridDim.x*blockDim.x;
    for (; i < n; i += stride) {
        float s5 = 1.f/(1.f+__expf(-h5[i]));
        float s6 = 1.f/(1.f+__expf(-h6[i]));
        float e5 = __expf(s5), e6 = __expf(s6);
        float w = e5/(e5+e6);
        out[i] = w*o1[i] + (1.f-w)*o2[i] + x[i];
    }
}

// ---------------- host ----------------
static inline void gemm_launch(const float* W, long wBS, const float* In, long inBS,
                               const float* bias, const float* Add, long addBS,
                               float* Out, long outBS, int M, int N, int K)
{
    dim3 grid(N/128, M/128, BB);
    sgemm128<<<grid, 256>>>(W, wBS, In, inBS, bias, Add, addBS, Out, outBS, M, N, K);
}

extern "C" void kernel_launch(void* const* d_in, const int* in_sizes, int n_in,
                              void* d_out, int out_size)
{
    (void)in_sizes; (void)n_in; (void)out_size;
    const float* x    = (const float*)d_in[0];
    const float* y    = (const float*)d_in[1];
    const float* z    = (const float*)d_in[2];
    const float* m    = (const float*)d_in[3];
    const float* Wv   = (const float*)d_in[4];
    const float* Wv2  = (const float*)d_in[5];
    const float* Wq   = (const float*)d_in[6];
    const float* bq   = (const float*)d_in[7];
    const float* Wk   = (const float*)d_in[8];
    const float* bk   = (const float*)d_in[9];
    const float* Wq2  = (const float*)d_in[10];
    const float* bq2  = (const float*)d_in[11];
    const float* Wk2  = (const float*)d_in[12];
    const float* bk2  = (const float*)d_in[13];
    const float* Win1 = (const float*)d_in[14];
    const float* bin1 = (const float*)d_in[15];
    const float* Win3 = (const float*)d_in[16];
    const float* bin3 = (const float*)d_in[17];
    const float* Wtr  = (const float*)d_in[18];
    const float* btr  = (const float*)d_in[19];
    const float* Wout2= (const float*)d_in[20];
    const float* bout2= (const float*)d_in[21];
    const float* Wout3= (const float*)d_in[22];
    const float* bout3= (const float*)d_in[23];
    const float* Wfc  = (const float*)d_in[24];
    const float* bfc  = (const float*)d_in[25];
    const float* gamma  = (const float*)d_in[26];
    const float* gamma2 = (const float*)d_in[27];
    float* out = (float*)d_out;

    float *fmz, *yv, *fmzy, *v2, *q1, *k1, *q2, *k2, *vt1, *vt2, *os1, *os2, *H13, *Htra, *H5, *H6;
    cudaGetSymbolAddress((void**)&fmz,  g_fmz);
    cudaGetSymbolAddress((void**)&yv,   g_yv);
    cudaGetSymbolAddress((void**)&fmzy, g_fmzy);
    cudaGetSymbolAddress((void**)&v2,   g_v2);
    cudaGetSymbolAddress((void**)&q1,   g_q1);
    cudaGetSymbolAddress((void**)&k1,   g_k1);
    cudaGetSymbolAddress((void**)&q2,   g_q2);
    cudaGetSymbolAddress((void**)&k2,   g_k2);
    cudaGetSymbolAddress((void**)&vt1,  g_vt1);
    cudaGetSymbolAddress((void**)&vt2,  g_vt2);
    cudaGetSymbolAddress((void**)&os1,  g_os1);
    cudaGetSymbolAddress((void**)&os2,  g_os2);
    cudaGetSymbolAddress((void**)&H13,  g_H13);
    cudaGetSymbolAddress((void**)&Htra, g_Htra);
    cudaGetSymbolAddress((void**)&H5,   g_H5);
    cudaGetSymbolAddress((void**)&H6,   g_H6);

    const long CN = (long)CC*NN;

    prep_kernel<<<dim3(8, BB), 256>>>(Wv, z, m, Wfc, bfc, fmz);
    gemm_launch(Wv, 0, y, CN, 0, 0, 0, yv, CN, CC, NN, CC);
    gemm_launch(fmz, (long)CC*CC, yv, CN, 0, yv, CN, fmzy, CN, CC, NN, CC);
    gemm_launch(Wv2, 0, x,    CN, 0,   0, 0, v2, CN, CC, NN, CC);
    gemm_launch(Wq,  0, x,    CN, bq,  0, 0, q1, CN, CC, NN, CC);
    gemm_launch(Wk,  0, fmzy, CN, bk,  0, 0, k1, CN, CC, NN, CC);
    gemm_launch(Wq2, 0, x,    CN, bq2, 0, 0, q2, CN, CC, NN, CC);
    gemm_launch(Wk2, 0, x,    CN, bk2, 0, 0, k2, CN, CC, NN, CC);

    // V transposes for paired-c attention loads
    transpose_kernel<<<dim3(NN/32, CC/32, BB), dim3(32,8)>>>(fmzy, vt1);
    transpose_kernel<<<dim3(NN/32, CC/32, BB), dim3(32,8)>>>(v2,   vt2);

    // both attention branches in one launch
    attn_kernel<<<dim3(NN/64, BB, 2), 256>>>(q1, k1, vt1, gamma,  os1,
                                             q2, k2, vt2, gamma2, os2);

    gemm_launch(Win1, 0, os1, CN, bin1, 0, 0, H13,          2*CN, CC,   NN, CC);
    gemm_launch(Win3, 0, os2, CN, bin3, 0, 0, H13 + CN,     2*CN, CC,   NN, CC);
    gemm_launch(Wtr,  0, H13, 2*CN, btr, 0, 0, Htra,        2*CN, 2*CC, NN, 2*CC);
    gemm_launch(Wout2,0, Htra,      2*CN, bout2, 0, 0, H5,  CN, CC, NN, CC);
    gemm_launch(Wout3,0, Htra + CN, 2*CN, bout3, 0, 0, H6,  CN, CC, NN, CC);
    final_kernel<<<1024, 256>>>(x, H5, H6, os1, os2, out, BB*CC*NN);
}

// round 8
// speedup vs baseline: 2.8726x; 2.6272x over previous
#include <cuda_runtime.h>
#include <cuda_bf16.h>

#define BB 4
#define CC 256
#define NN 4096

#define QT 64
#define KT 128
#define LDQ 72
#define LDK 72
#define LDP 136
#define LDV 136

typedef unsigned int uint32;
typedef unsigned long long ull;

// ---------------- f32x2 helpers (kept for sgemm from R4-passing kernel) ----------------
__device__ __forceinline__ ull pk2f(float a, float b) {
    ull r; asm("mov.b64 %0, {%1, %2};" : "=l"(r) : "f"(a), "f"(b)); return r;
}
__device__ __forceinline__ ull dup2f(float a) { return pk2f(a, a); }
__device__ __forceinline__ ull f2fma(ull a, ull b, ull c) {
    ull d; asm("fma.rn.f32x2 %0, %1, %2, %3;" : "=l"(d) : "l"(a), "l"(b), "l"(c)); return d;
}
__device__ __forceinline__ float2 upk2f(ull v) {
    float2 f; asm("mov.b64 {%0, %1}, %2;" : "=f"(f.x), "=f"(f.y) : "l"(v)); return f;
}

// ---------------- bf16 mma helper ----------------
__device__ __forceinline__ void mma16816(float* d, uint32 a0, uint32 a1, uint32 a2, uint32 a3,
                                         uint32 b0, uint32 b1) {
    asm volatile(
        "mma.sync.aligned.m16n8k16.row.col.f32.bf16.bf16.f32 "
        "{%0,%1,%2,%3}, {%4,%5,%6,%7}, {%8,%9}, {%0,%1,%2,%3};"
        : "+f"(d[0]), "+f"(d[1]), "+f"(d[2]), "+f"(d[3])
        : "r"(a0), "r"(a1), "r"(a2), "r"(a3), "r"(b0), "r"(b1));
}
__device__ __forceinline__ uint32 packbf(float x, float y) {
    __nv_bfloat162 h = __floats2bfloat162_rn(x, y);
    return *(uint32*)&h;
}

// ---------------- scratch (allocation-free: __device__ globals) ----------------
__device__ float g_fmz [BB*CC*CC];
__device__ float g_yv  [BB*CC*NN];
__device__ float g_fmzy[BB*CC*NN];
__device__ float g_v2  [BB*CC*NN];
__device__ float g_q1  [BB*CC*NN];
__device__ float g_k1  [BB*CC*NN];
__device__ float g_q2  [BB*CC*NN];
__device__ float g_k2  [BB*CC*NN];
__device__ float g_os1 [BB*CC*NN];
__device__ float g_os2 [BB*CC*NN];
__device__ float g_H13 [BB*2*CC*NN];
__device__ float g_Htra[BB*2*CC*NN];
__device__ float g_H5  [BB*CC*NN];
__device__ float g_H6  [BB*CC*NN];
__device__ __nv_bfloat16 g_qt1[BB*NN*CC];  // q transposed [b][n][c] bf16
__device__ __nv_bfloat16 g_kt1[BB*NN*CC];
__device__ __nv_bfloat16 g_qt2[BB*NN*CC];
__device__ __nv_bfloat16 g_kt2[BB*NN*CC];
__device__ __nv_bfloat16 g_vb1[BB*CC*NN];  // v in [b][c][n] bf16
__device__ __nv_bfloat16 g_vb2[BB*CC*NN];

// ---------------- tiny prep: mv, m_line_t, zv, fuse_mz ----------------
__global__ void prep_kernel(const float* __restrict__ Wv, const float* __restrict__ z,
                            const float* __restrict__ m_,  const float* __restrict__ Wfc,
                            const float* __restrict__ bfc, float* __restrict__ fmz)
{
    __shared__ float s_mlt[36*256];
    __shared__ float s_tmp[256*9];
    const int b  = blockIdx.y;
    const int c0 = blockIdx.x * 32;
    const int tid = threadIdx.x;

    for (int idx = tid; idx < 256*9; idx += 256) {
        int c = idx / 9, k = idx % 9;
        const float* wr = Wv + c*256;
        const float* mr = m_ + (long)(b*256)*9 + k;
        float s = 0.f;
        for (int i = 0; i < 256; i++) s += wr[i] * mr[i*9];
        s_tmp[idx] = s;
    }
    __syncthreads();
    for (int idx = tid; idx < 36*256; idx += 256) {
        int j = idx >> 8, d = idx & 255;
        float s = bfc[j];
        for (int k = 0; k < 9; k++) s += s_tmp[d*9+k] * Wfc[j*9+k];
        s_mlt[idx] = s;
    }
    __syncthreads();
    for (int idx = tid; idx < 32*36; idx += 256) {
        int cl = idx / 36, j = idx % 36;
        const float* wr = Wv + (c0+cl)*256;
        const float* zr = z + (long)(b*256)*36 + j;
        float s = 0.f;
        for (int i = 0; i < 256; i++) s += wr[i] * zr[i*36];
        s_tmp[idx] = s;
    }
    __syncthreads();
    for (int idx = tid; idx < 32*256; idx += 256) {
        int cl = idx >> 8, d = idx & 255;
        float s = 0.f;
        for (int j = 0; j < 36; j++) s += s_tmp[cl*36+j] * s_mlt[j*256+d];
        fmz[((long)(b*256) + c0 + cl)*256 + d] = s;
    }
}

// ---------------- fp32 [b][C][N] -> bf16 [b][N][C] (transpose + convert) ----------------
__global__ __launch_bounds__(256)
void convT_kernel(const float* __restrict__ A, __nv_bfloat16* __restrict__ At)
{
    __shared__ float t[32][33];
    const int b = blockIdx.z;
    const float* Ab = A + (long)b*CC*NN;
    __nv_bfloat16* Atb = At + (long)b*NN*CC;
    const int n0 = blockIdx.x*32, c0 = blockIdx.y*32;
    const int tx = threadIdx.x, ty = threadIdx.y;
    #pragma unroll
    for (int j = 0; j < 4; j++)
        t[ty+j*8][tx] = Ab[(long)(c0+ty+j*8)*NN + n0 + tx];
    __syncthreads();
    #pragma unroll
    for (int j = 0; j < 4; j++)
        Atb[(long)(n0+ty+j*8)*CC + c0 + tx] = __float2bfloat16(t[tx][ty+j*8]);
}

// ---------------- fp32 -> bf16 elementwise (same layout) ----------------
__global__ void conv_kernel(const float* __restrict__ A, __nv_bfloat16* __restrict__ B, int n)
{
    int i = (blockIdx.x*blockDim.x + threadIdx.x) * 4;
    const int stride = gridDim.x*blockDim.x*4;
    for (; i < n; i += stride) {
        float4 v = *(const float4*)&A[i];
        *(__nv_bfloat162*)&B[i]   = __floats2bfloat162_rn(v.x, v.y);
        *(__nv_bfloat162*)&B[i+2] = __floats2bfloat162_rn(v.z, v.w);
    }
}

// ---------------- generic batched SGEMM (f32x2 inner) — unchanged from R4 pass ----------------
__global__ __launch_bounds__(256)
void sgemm128(const float* __restrict__ W, long wBS,
              const float* __restrict__ In, long inBS,
              const float* __restrict__ bias,
              const float* __restrict__ Add, long addBS,
              float* __restrict__ Out, long outBS,
              int M, int N, int K)
{
    __shared__ float As[8][128];
    __shared__ float Bs[8][128];
    const int b = blockIdx.z;
    W   += (long)b * wBS;
    In  += (long)b * inBS;
    Out += (long)b * outBS;
    const float* AddB = Add ? (Add + (long)b * addBS) : (const float*)0;

    const int n0 = blockIdx.x * 128;
    const int m0 = blockIdx.y * 128;
    const int tid = threadIdx.x;
    const int tx = tid & 15, ty = tid >> 4;

    ull acc2[8][4];
    #pragma unroll
    for (int i = 0; i < 8; i++)
        #pragma unroll
        for (int j = 0; j < 4; j++) acc2[i][j] = 0ull;

    const int mmL = tid >> 1;
    const int kqL = (tid & 1) * 4;
    const int kkL = tid >> 5;
    const int nnL = (tid & 31) * 4;

    float4 aReg = *(const float4*)&W[(long)(m0+mmL)*K + kqL];
    float4 bReg = *(const float4*)&In[(long)kkL*N + n0 + nnL];

    for (int k0 = 0; k0 < K; k0 += 8) {
        As[kqL+0][mmL] = aReg.x; As[kqL+1][mmL] = aReg.y;
        As[kqL+2][mmL] = aReg.z; As[kqL+3][mmL] = aReg.w;
        *(float4*)&Bs[kkL][nnL] = bReg;
        __syncthreads();
        if (k0 + 8 < K) {
            aReg = *(const float4*)&W[(long)(m0+mmL)*K + k0 + 8 + kqL];
            bReg = *(const float4*)&In[(long)(k0+8+kkL)*N + n0 + nnL];
        }
        #pragma unroll
        for (int kk = 0; kk < 8; kk++) {
            float4 a0 = *(float4*)&As[kk][ty*8];
            float4 a1 = *(float4*)&As[kk][ty*8+4];
            float4 b0 = *(float4*)&Bs[kk][tx*8];
            float4 b1 = *(float4*)&Bs[kk][tx*8+4];
            ull bp0 = pk2f(b0.x,b0.y), bp1 = pk2f(b0.z,b0.w);
            ull bp2 = pk2f(b1.x,b1.y), bp3 = pk2f(b1.z,b1.w);
            float av[8] = {a0.x,a0.y,a0.z,a0.w,a1.x,a1.y,a1.z,a1.w};
            #pragma unroll
            for (int i = 0; i < 8; i++) {
                ull ad = dup2f(av[i]);
                acc2[i][0] = f2fma(ad, bp0, acc2[i][0]);
                acc2[i][1] = f2fma(ad, bp1, acc2[i][1]);
                acc2[i][2] = f2fma(ad, bp2, acc2[i][2]);
                acc2[i][3] = f2fma(ad, bp3, acc2[i][3]);
            }
        }
        __syncthreads();
    }
    #pragma unroll
    for (int i = 0; i < 8; i++) {
        const int mrow = m0 + ty*8 + i;
        const float bi = bias ? bias[mrow] : 0.f;
        #pragma unroll
        for (int jp = 0; jp < 4; jp++) {
            const int ncol = n0 + tx*8 + jp*2;
            float2 v = upk2f(acc2[i][jp]);
            v.x += bi; v.y += bi;
            if (AddB) {
                float2 ad = *(const float2*)&AddB[(long)mrow*N + ncol];
                v.x += ad.x; v.y += ad.y;
            }
            *(float2*)&Out[(long)mrow*N + ncol] = v;
        }
    }
}

// ---------------- tensor-core streaming attention (both branches) ----------------
// No-max softmax (logits tiny). 64 queries/CTA, key tiles of 128.
// Qt/Kt: bf16 [b][n][c]; Vb: bf16 [b][c][n]. Out fp32 [b][c][n], gamma folded.
// 8 warps = 4 q-groups x 2 halves. grid (NN/64, BB, 2), 256 threads.
__global__ __launch_bounds__(256)
void attn_tc_kernel(const __nv_bfloat16* __restrict__ Qt1, const __nv_bfloat16* __restrict__ Kt1,
                    const __nv_bfloat16* __restrict__ Vb1, const float* __restrict__ g1p,
                    float* __restrict__ O1,
                    const __nv_bfloat16* __restrict__ Qt2, const __nv_bfloat16* __restrict__ Kt2,
                    const __nv_bfloat16* __restrict__ Vb2, const float* __restrict__ g2p,
                    float* __restrict__ O2)
{
    __shared__ __nv_bfloat16 sQK[QT*LDQ + KT*LDK];   // Qs | Ks ; Vs overlays from 0
    __shared__ __nv_bfloat16 sP[QT*LDP];
    __shared__ float denom[QT];

    const int br = blockIdx.z;
    const __nv_bfloat16* Qt = br ? Qt2 : Qt1;
    const __nv_bfloat16* Kt = br ? Kt2 : Kt1;
    const __nv_bfloat16* Vb = br ? Vb2 : Vb1;
    const float* gp = br ? g2p : g1p;
    float* Out      = br ? O2  : O1;

    const int b  = blockIdx.y;
    const int q0 = blockIdx.x * QT;
    Qt += (long)b*NN*CC;
    Kt += (long)b*NN*CC;
    Vb += (long)b*CC*NN;
    Out+= (long)b*CC*NN;

    const int tid  = threadIdx.x;
    const int wid  = tid >> 5, lane = tid & 31;
    const int grp  = lane >> 2, qr = lane & 3;
    const int qg   = wid & 3,  half = wid >> 2;

    __nv_bfloat16* Qs = sQK;
    __nv_bfloat16* Ks = sQK + QT*LDQ;
    __nv_bfloat16* Vs = sQK;            // overlay (phase 2 only)

    if (tid < QT) denom[tid] = 0.f;

    float O[4][4][4];                   // [c-chunk][nf][4]
    #pragma unroll
    for (int a = 0; a < 4; a++)
        #pragma unroll
        for (int c = 0; c < 4; c++)
            #pragma unroll
            for (int d = 0; d < 4; d++) O[a][c][d] = 0.f;
    float dsum0 = 0.f, dsum1 = 0.f;

    // loader indices
    const int qlr = tid >> 2, qlc = (tid & 3) * 16;    // Qs: 64 rows x 64 cols
    const int klr = tid >> 1, klc = (tid & 1) * 32;    // Ks: 128 rows x 64 cols
    const int vlr = tid >> 2, vlc = (tid & 3) * 32;    // Vs: 64 rows x 128 cols

    for (int kt = 0; kt < NN/KT; kt++) {
        const int k0 = kt * KT;
        float S[8][4];
        #pragma unroll
        for (int i = 0; i < 8; i++)
            #pragma unroll
            for (int j = 0; j < 4; j++) S[i][j] = 0.f;

        // ---- phase 1: S[64q][128k] over C in chunks of 64 ----
        for (int cc = 0; cc < 4; cc++) {
            const int c0 = cc * 64;
            __syncthreads();   // prior consumers of sQK done
            *(float4*)&Qs[qlr*LDQ + qlc]     = *(const float4*)&Qt[(long)(q0+qlr)*CC + c0 + qlc];
            *(float4*)&Qs[qlr*LDQ + qlc + 8] = *(const float4*)&Qt[(long)(q0+qlr)*CC + c0 + qlc + 8];
            {
                const __nv_bfloat16* src = &Kt[(long)(k0+klr)*CC + c0 + klc];
                *(float4*)&Ks[klr*LDK + klc]      = *(const float4*)&src[0];
                *(float4*)&Ks[klr*LDK + klc + 8]  = *(const float4*)&src[8];
                *(float4*)&Ks[klr*LDK + klc + 16] = *(const float4*)&src[16];
                *(float4*)&Ks[klr*LDK + klc + 24] = *(const float4*)&src[24];
            }
            __syncthreads();
            #pragma unroll
            for (int ks = 0; ks < 4; ks++) {
                const int ar = qg*16 + grp;
                const int ac = ks*16 + 2*qr;
                uint32 a0 = *(const uint32*)&Qs[ar*LDQ + ac];
                uint32 a1 = *(const uint32*)&Qs[(ar+8)*LDQ + ac];
                uint32 a2 = *(const uint32*)&Qs[ar*LDQ + ac + 8];
                uint32 a3 = *(const uint32*)&Qs[(ar+8)*LDQ + ac + 8];
                #pragma unroll
                for (int nf = 0; nf < 8; nf++) {
                    const int brow = half*64 + nf*8 + grp;
                    uint32 b0 = *(const uint32*)&Ks[brow*LDK + ac];
                    uint32 b1 = *(const uint32*)&Ks[brow*LDK + ac + 8];
                    mma16816(S[nf], a0, a1, a2, a3, b0, b1);
                }
            }
        }

        // ---- exp -> sP (disjoint region; no sync needed before writes) ----
        #pragma unroll
        for (int nf = 0; nf < 8; nf++) {
            float e0 = __expf(S[nf][0]), e1 = __expf(S[nf][1]);
            float e2 = __expf(S[nf][2]), e3 = __expf(S[nf][3]);
            dsum0 += e0 + e1;
            dsum1 += e2 + e3;
            const int row = qg*16 + grp;
            const int col = half*64 + nf*8 + 2*qr;
            *(uint32*)&sP[row*LDP + col]     = packbf(e0, e1);
            *(uint32*)&sP[(row+8)*LDP + col] = packbf(e2, e3);
        }

        // ---- phase 2: O[64q][256c] += P @ V^T, c chunks of 64 ----
        for (int cc = 0; cc < 4; cc++) {
            __syncthreads();   // sP visible (cc=0) / previous Vs reads done
            {
                const __nv_bfloat16* src = &Vb[(long)(cc*64 + vlr)*NN + k0 + vlc];
                *(float4*)&Vs[vlr*LDV + vlc]      = *(const float4*)&src[0];
                *(float4*)&Vs[vlr*LDV + vlc + 8]  = *(const float4*)&src[8];
                *(float4*)&Vs[vlr*LDV + vlc + 16] = *(const float4*)&src[16];
                *(float4*)&Vs[vlr*LDV + vlc + 24] = *(const float4*)&src[24];
            }
            __syncthreads();
            #pragma unroll
            for (int ks = 0; ks < 8; ks++) {
                const int ar = qg*16 + grp;
                const int ac = ks*16 + 2*qr;
                uint32 a0 = *(const uint32*)&sP[ar*LDP + ac];
                uint32 a1 = *(const uint32*)&sP[(ar+8)*LDP + ac];
                uint32 a2 = *(const uint32*)&sP[ar*LDP + ac + 8];
                uint32 a3 = *(const uint32*)&sP[(ar+8)*LDP + ac + 8];
                #pragma unroll
                for (int nf = 0; nf < 4; nf++) {
                    const int brow = half*32 + nf*8 + grp;   // c-local row
                    uint32 b0 = *(const uint32*)&Vs[brow*LDV + ac];
                    uint32 b1 = *(const uint32*)&Vs[brow*LDV + ac + 8];
                    mma16816(O[cc][nf], a0, a1, a2, a3, b0, b1);
                }
            }
        }
    }

    atomicAdd(&denom[qg*16 + grp],     dsum0);
    atomicAdd(&denom[qg*16 + grp + 8], dsum1);
    __syncthreads();

    const float g = gp[0];
    const float inv0 = g / denom[qg*16 + grp];
    const float inv1 = g / denom[qg*16 + grp + 8];
    const int n = q0 + qg*16 + grp;
    #pragma unroll
    for (int cc = 0; cc < 4; cc++) {
        #pragma unroll
        for (int nf = 0; nf < 4; nf++) {
            const long c = cc*64 + half*32 + nf*8 + 2*qr;
            Out[c*NN + n]           = O[cc][nf][0] * inv0;
            Out[(c+1)*NN + n]       = O[cc][nf][1] * inv0;
            Out[c*NN + n + 8]       = O[cc][nf][2] * inv1;
            Out[(c+1)*NN + n + 8]   = O[cc][nf][3] * inv1;
        }
    }
}

// ---------------- epilogue ----------------
__global__ void final_kernel(const float* __restrict__ x,  const float* __restrict__ h5,
                             const float* __restrict__ h6, const float* __restrict__ o1,
                             const float* __restrict__ o2, float* __restrict__ out, int n)
{
    int i = blockIdx.x*blockDim.x + threadIdx.x;
    const int stride = gridDim.x*blockDim.x;
    for (; i < n; i += stride) {
        float s5 = 1.f/(1.f+__expf(-h5[i]));
        float s6 = 1.f/(1.f+__expf(-h6[i]));
        float e5 = __expf(s5), e6 = __expf(s6);
        float w = e5/(e5+e6);
        out[i] = w*o1[i] + (1.f-w)*o2[i] + x[i];
    }
}

// ---------------- host ----------------
static inline void gemm_launch(const float* W, long wBS, const float* In, long inBS,
                               const float* bias, const float* Add, long addBS,
                               float* Out, long outBS, int M, int N, int K)
{
    dim3 grid(N/128, M/128, BB);
    sgemm128<<<grid, 256>>>(W, wBS, In, inBS, bias, Add, addBS, Out, outBS, M, N, K);
}

extern "C" void kernel_launch(void* const* d_in, const int* in_sizes, int n_in,
                              void* d_out, int out_size)
{
    (void)in_sizes; (void)n_in; (void)out_size;
    const float* x    = (const float*)d_in[0];
    const float* y    = (const float*)d_in[1];
    const float* z    = (const float*)d_in[2];
    const float* m    = (const float*)d_in[3];
    const float* Wv   = (const float*)d_in[4];
    const float* Wv2  = (const float*)d_in[5];
    const float* Wq   = (const float*)d_in[6];
    const float* bq   = (const float*)d_in[7];
    const float* Wk   = (const float*)d_in[8];
    const float* bk   = (const float*)d_in[9];
    const float* Wq2  = (const float*)d_in[10];
    const float* bq2  = (const float*)d_in[11];
    const float* Wk2  = (const float*)d_in[12];
    const float* bk2  = (const float*)d_in[13];
    const float* Win1 = (const float*)d_in[14];
    const float* bin1 = (const float*)d_in[15];
    const float* Win3 = (const float*)d_in[16];
    const float* bin3 = (const float*)d_in[17];
    const float* Wtr  = (const float*)d_in[18];
    const float* btr  = (const float*)d_in[19];
    const float* Wout2= (const float*)d_in[20];
    const float* bout2= (const float*)d_in[21];
    const float* Wout3= (const float*)d_in[22];
    const float* bout3= (const float*)d_in[23];
    const float* Wfc  = (const float*)d_in[24];
    const float* bfc  = (const float*)d_in[25];
    const float* gamma  = (const float*)d_in[26];
    const float* gamma2 = (const float*)d_in[27];
    float* out = (float*)d_out;

    float *fmz, *yv, *fmzy, *v2, *q1, *k1, *q2, *k2, *os1, *os2, *H13, *Htra, *H5, *H6;
    __nv_bfloat16 *qt1, *kt1, *qt2, *kt2, *vb1, *vb2;
    cudaGetSymbolAddress((void**)&fmz,  g_fmz);
    cudaGetSymbolAddress((void**)&yv,   g_yv);
    cudaGetSymbolAddress((void**)&fmzy, g_fmzy);
    cudaGetSymbolAddress((void**)&v2,   g_v2);
    cudaGetSymbolAddress((void**)&q1,   g_q1);
    cudaGetSymbolAddress((void**)&k1,   g_k1);
    cudaGetSymbolAddress((void**)&q2,   g_q2);
    cudaGetSymbolAddress((void**)&k2,   g_k2);
    cudaGetSymbolAddress((void**)&os1,  g_os1);
    cudaGetSymbolAddress((void**)&os2,  g_os2);
    cudaGetSymbolAddress((void**)&H13,  g_H13);
    cudaGetSymbolAddress((void**)&Htra, g_Htra);
    cudaGetSymbolAddress((void**)&H5,   g_H5);
    cudaGetSymbolAddress((void**)&H6,   g_H6);
    cudaGetSymbolAddress((void**)&qt1,  g_qt1);
    cudaGetSymbolAddress((void**)&kt1,  g_kt1);
    cudaGetSymbolAddress((void**)&qt2,  g_qt2);
    cudaGetSymbolAddress((void**)&kt2,  g_kt2);
    cudaGetSymbolAddress((void**)&vb1,  g_vb1);
    cudaGetSymbolAddress((void**)&vb2,  g_vb2);

    const long CN = (long)CC*NN;
    const int total = BB*CC*NN;

    prep_kernel<<<dim3(8, BB), 256>>>(Wv, z, m, Wfc, bfc, fmz);
    gemm_launch(Wv, 0, y, CN, 0, 0, 0, yv, CN, CC, NN, CC);
    gemm_launch(fmz, (long)CC*CC, yv, CN, 0, yv, CN, fmzy, CN, CC, NN, CC);
    gemm_launch(Wv2, 0, x,    CN, 0,   0, 0, v2, CN, CC, NN, CC);
    gemm_launch(Wq,  0, x,    CN, bq,  0, 0, q1, CN, CC, NN, CC);
    gemm_launch(Wk,  0, fmzy, CN, bk,  0, 0, k1, CN, CC, NN, CC);
    gemm_launch(Wq2, 0, x,    CN, bq2, 0, 0, q2, CN, CC, NN, CC);
    gemm_launch(Wk2, 0, x,    CN, bk2, 0, 0, k2, CN, CC, NN, CC);

    // bf16 conversions: Q/K transposed to [n][c], V kept [c][n]
    dim3 tg(NN/32, CC/32, BB), tb(32, 8);
    convT_kernel<<<tg, tb>>>(q1, qt1);
    convT_kernel<<<tg, tb>>>(k1, kt1);
    convT_kernel<<<tg, tb>>>(q2, qt2);
    convT_kernel<<<tg, tb>>>(k2, kt2);
    conv_kernel<<<1024, 256>>>(fmzy, vb1, total);
    conv_kernel<<<1024, 256>>>(v2,   vb2, total);

    // tensor-core attention, both branches
    attn_tc_kernel<<<dim3(NN/QT, BB, 2), 256>>>(qt1, kt1, vb1, gamma,  os1,
                                                qt2, kt2, vb2, gamma2, os2);

    gemm_launch(Win1, 0, os1, CN, bin1, 0, 0, H13,          2*CN, CC,   NN, CC);
    gemm_launch(Win3, 0, os2, CN, bin3, 0, 0, H13 + CN,     2*CN, CC,   NN, CC);
    gemm_launch(Wtr,  0, H13, 2*CN, btr, 0, 0, Htra,        2*CN, 2*CC, NN, 2*CC);
    gemm_launch(Wout2,0, Htra,      2*CN, bout2, 0, 0, H5,  CN, CC, NN, CC);
    gemm_launch(Wout3,0, Htra + CN, 2*CN, bout3, 0, 0, H6,  CN, CC, NN, CC);
    final_kernel<<<1024, 256>>>(x, H5, H6, os1, os2, out, BB*CC*NN);
}

// round 9
// speedup vs baseline: 4.4130x; 1.5362x over previous
#include <cuda_runtime.h>
#include <cuda_bf16.h>

#define BB 4
#define CC 256
#define NN 4096

#define QT 64
#define KT 128
#define LDQ 72
#define LDK 72
#define LDP 136
#define LDV 136
#define LDG_ 40   // tc_gemm smem pad (32+8)

typedef unsigned int uint32;

// ---------------- bf16 mma helper (validated mapping) ----------------
__device__ __forceinline__ void mma16816(float* d, uint32 a0, uint32 a1, uint32 a2, uint32 a3,
                                         uint32 b0, uint32 b1) {
    asm volatile(
        "mma.sync.aligned.m16n8k16.row.col.f32.bf16.bf16.f32 "
        "{%0,%1,%2,%3}, {%4,%5,%6,%7}, {%8,%9}, {%0,%1,%2,%3};"
        : "+f"(d[0]), "+f"(d[1]), "+f"(d[2]), "+f"(d[3])
        : "r"(a0), "r"(a1), "r"(a2), "r"(a3), "r"(b0), "r"(b1));
}
__device__ __forceinline__ uint32 packbf(float x, float y) {
    __nv_bfloat162 h = __floats2bfloat162_rn(x, y);
    return *(uint32*)&h;
}

// ---------------- scratch (allocation-free: __device__ globals) ----------------
__device__ __nv_bfloat16 g_fmzb[BB*CC*CC];     // (I + fuse_mz) bf16
__device__ __nv_bfloat16 g_xT  [BB*NN*CC];
__device__ __nv_bfloat16 g_yT  [BB*NN*CC];
__device__ __nv_bfloat16 g_yvT [BB*NN*CC];
__device__ __nv_bfloat16 g_fmzyT[BB*NN*CC];
__device__ __nv_bfloat16 g_qt1 [BB*NN*CC];
__device__ __nv_bfloat16 g_kt1 [BB*NN*CC];
__device__ __nv_bfloat16 g_qt2 [BB*NN*CC];
__device__ __nv_bfloat16 g_kt2 [BB*NN*CC];
__device__ __nv_bfloat16 g_vb1 [BB*CC*NN];
__device__ __nv_bfloat16 g_vb2 [BB*CC*NN];
__device__ __nv_bfloat16 g_os1T[BB*NN*CC];
__device__ __nv_bfloat16 g_os2T[BB*NN*CC];
__device__ __nv_bfloat16 g_H13T[BB*NN*2*CC];
__device__ __nv_bfloat16 g_HtraT[BB*NN*2*CC];
__device__ float g_os1[BB*CC*NN];
__device__ float g_os2[BB*CC*NN];
__device__ float g_H5 [BB*CC*NN];
__device__ float g_H6 [BB*CC*NN];
// bf16 weights
__device__ __nv_bfloat16 g_Wvb  [CC*CC];
__device__ __nv_bfloat16 g_Wv2b [CC*CC];
__device__ __nv_bfloat16 g_Wqb  [CC*CC];
__device__ __nv_bfloat16 g_Wkb  [CC*CC];
__device__ __nv_bfloat16 g_Wq2b [CC*CC];
__device__ __nv_bfloat16 g_Wk2b [CC*CC];
__device__ __nv_bfloat16 g_Win1b[CC*CC];
__device__ __nv_bfloat16 g_Win3b[CC*CC];
__device__ __nv_bfloat16 g_Wout2b[CC*CC];
__device__ __nv_bfloat16 g_Wout3b[CC*CC];
__device__ __nv_bfloat16 g_Wtrb [2*CC*2*CC];

// ---------------- tiny prep: mv, m_line_t, zv, fuse_mz (+I, bf16 out) ----------------
__global__ void prep_kernel(const float* __restrict__ Wv, const float* __restrict__ z,
                            const float* __restrict__ m_,  const float* __restrict__ Wfc,
                            const float* __restrict__ bfc, __nv_bfloat16* __restrict__ fmzb)
{
    __shared__ float s_mlt[36*256];
    __shared__ float s_tmp[256*9];
    const int b  = blockIdx.y;
    const int c0 = blockIdx.x * 32;
    const int tid = threadIdx.x;

    for (int idx = tid; idx < 256*9; idx += 256) {
        int c = idx / 9, k = idx % 9;
        const float* wr = Wv + c*256;
        const float* mr = m_ + (long)(b*256)*9 + k;
        float s = 0.f;
        for (int i = 0; i < 256; i++) s += wr[i] * mr[i*9];
        s_tmp[idx] = s;
    }
    __syncthreads();
    for (int idx = tid; idx < 36*256; idx += 256) {
        int j = idx >> 8, d = idx & 255;
        float s = bfc[j];
        for (int k = 0; k < 9; k++) s += s_tmp[d*9+k] * Wfc[j*9+k];
        s_mlt[idx] = s;
    }
    __syncthreads();
    for (int idx = tid; idx < 32*36; idx += 256) {
        int cl = idx / 36, j = idx % 36;
        const float* wr = Wv + (c0+cl)*256;
        const float* zr = z + (long)(b*256)*36 + j;
        float s = 0.f;
        for (int i = 0; i < 256; i++) s += wr[i] * zr[i*36];
        s_tmp[idx] = s;
    }
    __syncthreads();
    for (int idx = tid; idx < 32*256; idx += 256) {
        int cl = idx >> 8, d = idx & 255;
        float s = 0.f;
        for (int j = 0; j < 36; j++) s += s_tmp[cl*36+j] * s_mlt[j*256+d];
        if (d == c0 + cl) s += 1.f;   // fold the +yv residual as identity
        fmzb[((long)(b*256) + c0 + cl)*256 + d] = __float2bfloat16(s);
    }
}

// ---------------- fp32 [b][C][N] -> bf16 [b][N][C] (transpose + convert) ----------------
__global__ __launch_bounds__(256)
void convT_kernel(const float* __restrict__ A, __nv_bfloat16* __restrict__ At)
{
    __shared__ float t[32][33];
    const int b = blockIdx.z;
    const float* Ab = A + (long)b*CC*NN;
    __nv_bfloat16* Atb = At + (long)b*NN*CC;
    const int n0 = blockIdx.x*32, c0 = blockIdx.y*32;
    const int tx = threadIdx.x, ty = threadIdx.y;
    #pragma unroll
    for (int j = 0; j < 4; j++)
        t[ty+j*8][tx] = Ab[(long)(c0+ty+j*8)*NN + n0 + tx];
    __syncthreads();
    #pragma unroll
    for (int j = 0; j < 4; j++)
        Atb[(long)(n0+ty+j*8)*CC + c0 + tx] = __float2bfloat16(t[tx][ty+j*8]);
}

// ---------------- fp32 -> bf16 elementwise ----------------
__global__ void conv_kernel(const float* __restrict__ A, __nv_bfloat16* __restrict__ B, int n)
{
    int i = (blockIdx.x*blockDim.x + threadIdx.x) * 4;
    const int stride = gridDim.x*blockDim.x*4;
    for (; i < n; i += stride) {
        float4 v = *(const float4*)&A[i];
        *(__nv_bfloat162*)&B[i]   = __floats2bfloat162_rn(v.x, v.y);
        *(__nv_bfloat162*)&B[i+2] = __floats2bfloat162_rn(v.z, v.w);
    }
}

// ---------------- generic bf16 tensor-core GEMM ----------------
// D[M][N] = A[M][K] @ B[N][K]^T (+bias). 128x128 tile, BK=32, 8 warps (4x2).
// biasMode: 0 none, 1 row (bias[m]), 2 col (bias[n]). outBf16: output dtype.
__global__ __launch_bounds__(256)
void tc_gemm(const __nv_bfloat16* __restrict__ A, long aBS, int lda,
             const __nv_bfloat16* __restrict__ Bp, long bBS, int ldb,
             const float* __restrict__ bias, int biasMode,
             void* __restrict__ OutP, long oBS, int ldo, int outBf16,
             int M, int N, int K)
{
    __shared__ __nv_bfloat16 As[128*LDG_];
    __shared__ __nv_bfloat16 Bs[128*LDG_];
    const int b = blockIdx.z;
    A  += (long)b*aBS;
    Bp += (long)b*bBS;
    const int n0 = blockIdx.x*128, m0 = blockIdx.y*128;
    const int tid = threadIdx.x;
    const int lane = tid & 31, wid = tid >> 5;
    const int grp = lane >> 2, qr = lane & 3;
    const int wm = wid >> 1, wn = wid & 1;

    float D[2][8][4];
    #pragma unroll
    for (int i = 0; i < 2; i++)
        #pragma unroll
        for (int j = 0; j < 8; j++)
            #pragma unroll
            for (int k = 0; k < 4; k++) D[i][j][k] = 0.f;

    const int lr = tid >> 1, lc = (tid & 1) * 16;
    float4 pa0 = *(const float4*)&A [(long)(m0+lr)*lda + lc];
    float4 pa1 = *(const float4*)&A [(long)(m0+lr)*lda + lc + 8];
    float4 pb0 = *(const float4*)&Bp[(long)(n0+lr)*ldb + lc];
    float4 pb1 = *(const float4*)&Bp[(long)(n0+lr)*ldb + lc + 8];

    for (int k0 = 0; k0 < K; k0 += 32) {
        *(float4*)&As[lr*LDG_ + lc]     = pa0;
        *(float4*)&As[lr*LDG_ + lc + 8] = pa1;
        *(float4*)&Bs[lr*LDG_ + lc]     = pb0;
        *(float4*)&Bs[lr*LDG_ + lc + 8] = pb1;
        __syncthreads();
        if (k0 + 32 < K) {
            pa0 = *(const float4*)&A [(long)(m0+lr)*lda + k0 + 32 + lc];
            pa1 = *(const float4*)&A [(long)(m0+lr)*lda + k0 + 32 + lc + 8];
            pb0 = *(const float4*)&Bp[(long)(n0+lr)*ldb + k0 + 32 + lc];
            pb1 = *(const float4*)&Bp[(long)(n0+lr)*ldb + k0 + 32 + lc + 8];
        }
        #pragma unroll
        for (int kk = 0; kk < 2; kk++) {
            const int kb = kk*16 + 2*qr;
            uint32 aF[2][4];
            #pragma unroll
            for (int mi = 0; mi < 2; mi++) {
                const int ar = wm*32 + mi*16 + grp;
                aF[mi][0] = *(const uint32*)&As[ar*LDG_ + kb];
                aF[mi][1] = *(const uint32*)&As[(ar+8)*LDG_ + kb];
                aF[mi][2] = *(const uint32*)&As[ar*LDG_ + kb + 8];
                aF[mi][3] = *(const uint32*)&As[(ar+8)*LDG_ + kb + 8];
            }
            #pragma unroll
            for (int nf = 0; nf < 8; nf++) {
                const int brr = wn*64 + nf*8 + grp;
                uint32 b0 = *(const uint32*)&Bs[brr*LDG_ + kb];
                uint32 b1 = *(const uint32*)&Bs[brr*LDG_ + kb + 8];
                mma16816(D[0][nf], aF[0][0], aF[0][1], aF[0][2], aF[0][3], b0, b1);
                mma16816(D[1][nf], aF[1][0], aF[1][1], aF[1][2], aF[1][3], b0, b1);
            }
        }
        __syncthreads();
    }

    #pragma unroll
    for (int mi = 0; mi < 2; mi++) {
        const int mr = m0 + wm*32 + mi*16 + grp;
        #pragma unroll
        for (int nf = 0; nf < 8; nf++) {
            const int nc = n0 + wn*64 + nf*8 + 2*qr;
            float d0 = D[mi][nf][0], d1 = D[mi][nf][1];
            float d2 = D[mi][nf][2], d3 = D[mi][nf][3];
            if (biasMode == 1) {
                float bi0 = bias[mr], bi8 = bias[mr+8];
                d0 += bi0; d1 += bi0; d2 += bi8; d3 += bi8;
            } else if (biasMode == 2) {
                float bc0 = bias[nc], bc1 = bias[nc+1];
                d0 += bc0; d1 += bc1; d2 += bc0; d3 += bc1;
            }
            if (outBf16) {
                __nv_bfloat16* Out = (__nv_bfloat16*)OutP + (long)b*oBS;
                *(uint32*)&Out[(long)mr*ldo + nc]     = packbf(d0, d1);
                *(uint32*)&Out[(long)(mr+8)*ldo + nc] = packbf(d2, d3);
            } else {
                float* Out = (float*)OutP + (long)b*oBS;
                *(float2*)&Out[(long)mr*ldo + nc]     = make_float2(d0, d1);
                *(float2*)&Out[(long)(mr+8)*ldo + nc] = make_float2(d2, d3);
            }
        }
    }
}

// ---------------- tensor-core streaming attention (UNCHANGED from R8 pass) ----------------
__global__ __launch_bounds__(256)
void attn_tc_kernel(const __nv_bfloat16* __restrict__ Qt1, const __nv_bfloat16* __restrict__ Kt1,
                    const __nv_bfloat16* __restrict__ Vb1, const float* __restrict__ g1p,
                    float* __restrict__ O1,
                    const __nv_bfloat16* __restrict__ Qt2, const __nv_bfloat16* __restrict__ Kt2,
                    const __nv_bfloat16* __restrict__ Vb2, const float* __restrict__ g2p,
                    float* __restrict__ O2)
{
    __shared__ __nv_bfloat16 sQK[QT*LDQ + KT*LDK];
    __shared__ __nv_bfloat16 sP[QT*LDP];
    __shared__ float denom[QT];

    const int br = blockIdx.z;
    const __nv_bfloat16* Qt = br ? Qt2 : Qt1;
    const __nv_bfloat16* Kt = br ? Kt2 : Kt1;
    const __nv_bfloat16* Vb = br ? Vb2 : Vb1;
    const float* gp = br ? g2p : g1p;
    float* Out      = br ? O2  : O1;

    const int b  = blockIdx.y;
    const int q0 = blockIdx.x * QT;
    Qt += (long)b*NN*CC;
    Kt += (long)b*NN*CC;
    Vb += (long)b*CC*NN;
    Out+= (long)b*CC*NN;

    const int tid  = threadIdx.x;
    const int wid  = tid >> 5, lane = tid & 31;
    const int grp  = lane >> 2, qr = lane & 3;
    const int qg   = wid & 3,  half = wid >> 2;

    __nv_bfloat16* Qs = sQK;
    __nv_bfloat16* Ks = sQK + QT*LDQ;
    __nv_bfloat16* Vs = sQK;

    if (tid < QT) denom[tid] = 0.f;

    float O[4][4][4];
    #pragma unroll
    for (int a = 0; a < 4; a++)
        #pragma unroll
        for (int c = 0; c < 4; c++)
            #pragma unroll
            for (int d = 0; d < 4; d++) O[a][c][d] = 0.f;
    float dsum0 = 0.f, dsum1 = 0.f;

    const int qlr = tid >> 2, qlc = (tid & 3) * 16;
    const int klr = tid >> 1, klc = (tid & 1) * 32;
    const int vlr = tid >> 2, vlc = (tid & 3) * 32;

    for (int kt = 0; kt < NN/KT; kt++) {
        const int k0 = kt * KT;
        float S[8][4];
        #pragma unroll
        for (int i = 0; i < 8; i++)
            #pragma unroll
            for (int j = 0; j < 4; j++) S[i][j] = 0.f;

        for (int cc = 0; cc < 4; cc++) {
            const int c0 = cc * 64;
            __syncthreads();
            *(float4*)&Qs[qlr*LDQ + qlc]     = *(const float4*)&Qt[(long)(q0+qlr)*CC + c0 + qlc];
            *(float4*)&Qs[qlr*LDQ + qlc + 8] = *(const float4*)&Qt[(long)(q0+qlr)*CC + c0 + qlc + 8];
            {
                const __nv_bfloat16* src = &Kt[(long)(k0+klr)*CC + c0 + klc];
                *(float4*)&Ks[klr*LDK + klc]      = *(const float4*)&src[0];
                *(float4*)&Ks[klr*LDK + klc + 8]  = *(const float4*)&src[8];
                *(float4*)&Ks[klr*LDK + klc + 16] = *(const float4*)&src[16];
                *(float4*)&Ks[klr*LDK + klc + 24] = *(const float4*)&src[24];
            }
            __syncthreads();
            #pragma unroll
            for (int ks = 0; ks < 4; ks++) {
                const int ar = qg*16 + grp;
                const int ac = ks*16 + 2*qr;
                uint32 a0 = *(const uint32*)&Qs[ar*LDQ + ac];
                uint32 a1 = *(const uint32*)&Qs[(ar+8)*LDQ + ac];
                uint32 a2 = *(const uint32*)&Qs[ar*LDQ + ac + 8];
                uint32 a3 = *(const uint32*)&Qs[(ar+8)*LDQ + ac + 8];
                #pragma unroll
                for (int nf = 0; nf < 8; nf++) {
                    const int brow = half*64 + nf*8 + grp;
                    uint32 b0 = *(const uint32*)&Ks[brow*LDK + ac];
                    uint32 b1 = *(const uint32*)&Ks[brow*LDK + ac + 8];
                    mma16816(S[nf], a0, a1, a2, a3, b0, b1);
                }
            }
        }

        #pragma unroll
        for (int nf = 0; nf < 8; nf++) {
            float e0 = __expf(S[nf][0]), e1 = __expf(S[nf][1]);
            float e2 = __expf(S[nf][2]), e3 = __expf(S[nf][3]);
            dsum0 += e0 + e1;
            dsum1 += e2 + e3;
            const int row = qg*16 + grp;
            const int col = half*64 + nf*8 + 2*qr;
            *(uint32*)&sP[row*LDP + col]     = packbf(e0, e1);
            *(uint32*)&sP[(row+8)*LDP + col] = packbf(e2, e3);
        }

        for (int cc = 0; cc < 4; cc++) {
            __syncthreads();
            {
                const __nv_bfloat16* src = &Vb[(long)(cc*64 + vlr)*NN + k0 + vlc];
                *(float4*)&Vs[vlr*LDV + vlc]      = *(const float4*)&src[0];
                *(float4*)&Vs[vlr*LDV + vlc + 8]  = *(const float4*)&src[8];
                *(float4*)&Vs[vlr*LDV + vlc + 16] = *(const float4*)&src[16];
                *(float4*)&Vs[vlr*LDV + vlc + 24] = *(const float4*)&src[24];
            }
            __syncthreads();
            #pragma unroll
            for (int ks = 0; ks < 8; ks++) {
                const int ar = qg*16 + grp;
                const int ac = ks*16 + 2*qr;
                uint32 a0 = *(const uint32*)&sP[ar*LDP + ac];
                uint32 a1 = *(const uint32*)&sP[(ar+8)*LDP + ac];
                uint32 a2 = *(const uint32*)&sP[ar*LDP + ac + 8];
                uint32 a3 = *(const uint32*)&sP[(ar+8)*LDP + ac + 8];
                #pragma unroll
                for (int nf = 0; nf < 4; nf++) {
                    const int brow = half*32 + nf*8 + grp;
                    uint32 b0 = *(const uint32*)&Vs[brow*LDV + ac];
                    uint32 b1 = *(const uint32*)&Vs[brow*LDV + ac + 8];
                    mma16816(O[cc][nf], a0, a1, a2, a3, b0, b1);
                }
            }
        }
    }

    atomicAdd(&denom[qg*16 + grp],     dsum0);
    atomicAdd(&denom[qg*16 + grp + 8], dsum1);
    __syncthreads();

    const float g = gp[0];
    const float inv0 = g / denom[qg*16 + grp];
    const float inv1 = g / denom[qg*16 + grp + 8];
    const int n = q0 + qg*16 + grp;
    #pragma unroll
    for (int cc = 0; cc < 4; cc++) {
        #pragma unroll
        for (int nf = 0; nf < 4; nf++) {
            const long c = cc*64 + half*32 + nf*8 + 2*qr;
            Out[c*NN + n]           = O[cc][nf][0] * inv0;
            Out[(c+1)*NN + n]       = O[cc][nf][1] * inv0;
            Out[c*NN + n + 8]       = O[cc][nf][2] * inv1;
            Out[(c+1)*NN + n + 8]   = O[cc][nf][3] * inv1;
        }
    }
}

// ---------------- epilogue ----------------
__global__ void final_kernel(const float* __restrict__ x,  const float* __restrict__ h5,
                             const float* __restrict__ h6, const float* __restrict__ o1,
                             const float* __restrict__ o2, float* __restrict__ out, int n)
{
    int i = blockIdx.x*blockDim.x + threadIdx.x;
    const int stride = gridDim.x*blockDim.x;
    for (; i < n; i += stride) {
        float s5 = 1.f/(1.f+__expf(-h5[i]));
        float s6 = 1.f/(1.f+__expf(-h6[i]));
        float e5 = __expf(s5), e6 = __expf(s6);
        float w = e5/(e5+e6);
        out[i] = w*o1[i] + (1.f-w)*o2[i] + x[i];
    }
}

// ---------------- host ----------------
static inline void tc_launch(const __nv_bfloat16* A, long aBS, int lda,
                             const __nv_bfloat16* B, long bBS, int ldb,
                             const float* bias, int biasMode,
                             void* Out, long oBS, int ldo, int outBf16,
                             int M, int N, int K)
{
    dim3 grid(N/128, M/128, BB);
    tc_gemm<<<grid, 256>>>(A, aBS, lda, B, bBS, ldb, bias, biasMode,
                           Out, oBS, ldo, outBf16, M, N, K);
}

extern "C" void kernel_launch(void* const* d_in, const int* in_sizes, int n_in,
                              void* d_out, int out_size)
{
    (void)in_sizes; (void)n_in; (void)out_size;
    const float* x    = (const float*)d_in[0];
    const float* y    = (const float*)d_in[1];
    const float* z    = (const float*)d_in[2];
    const float* m    = (const float*)d_in[3];
    const float* Wv   = (const float*)d_in[4];
    const float* Wv2  = (const float*)d_in[5];
    const float* Wq   = (const float*)d_in[6];
    const float* bq   = (const float*)d_in[7];
    const float* Wk   = (const float*)d_in[8];
    const float* bk   = (const float*)d_in[9];
    const float* Wq2  = (const float*)d_in[10];
    const float* bq2  = (const float*)d_in[11];
    const float* Wk2  = (const float*)d_in[12];
    const float* bk2  = (const float*)d_in[13];
    const float* Win1 = (const float*)d_in[14];
    const float* bin1 = (const float*)d_in[15];
    const float* Win3 = (const float*)d_in[16];
    const float* bin3 = (const float*)d_in[17];
    const float* Wtr  = (const float*)d_in[18];
    const float* btr  = (const float*)d_in[19];
    const float* Wout2= (const float*)d_in[20];
    const float* bout2= (const float*)d_in[21];
    const float* Wout3= (const float*)d_in[22];
    const float* bout3= (const float*)d_in[23];
    const float* Wfc  = (const float*)d_in[24];
    const float* bfc  = (const float*)d_in[25];
    const float* gamma  = (const float*)d_in[26];
    const float* gamma2 = (const float*)d_in[27];
    float* out = (float*)d_out;

    __nv_bfloat16 *fmzb, *xT, *yT, *yvT, *fmzyT, *qt1, *kt1, *qt2, *kt2, *vb1, *vb2;
    __nv_bfloat16 *os1T, *os2T, *H13T, *HtraT;
    __nv_bfloat16 *Wvb, *Wv2b, *Wqb, *Wkb, *Wq2b, *Wk2b, *Win1b, *Win3b, *Wout2b, *Wout3b, *Wtrb;
    float *os1, *os2, *H5, *H6;
    cudaGetSymbolAddress((void**)&fmzb,  g_fmzb);
    cudaGetSymbolAddress((void**)&xT,    g_xT);
    cudaGetSymbolAddress((void**)&yT,    g_yT);
    cudaGetSymbolAddress((void**)&yvT,   g_yvT);
    cudaGetSymbolAddress((void**)&fmzyT, g_fmzyT);
    cudaGetSymbolAddress((void**)&qt1,   g_qt1);
    cudaGetSymbolAddress((void**)&kt1,   g_kt1);
    cudaGetSymbolAddress((void**)&qt2,   g_qt2);
    cudaGetSymbolAddress((void**)&kt2,   g_kt2);
    cudaGetSymbolAddress((void**)&vb1,   g_vb1);
    cudaGetSymbolAddress((void**)&vb2,   g_vb2);
    cudaGetSymbolAddress((void**)&os1T,  g_os1T);
    cudaGetSymbolAddress((void**)&os2T,  g_os2T);
    cudaGetSymbolAddress((void**)&H13T,  g_H13T);
    cudaGetSymbolAddress((void**)&HtraT, g_HtraT);
    cudaGetSymbolAddress((void**)&os1,   g_os1);
    cudaGetSymbolAddress((void**)&os2,   g_os2);
    cudaGetSymbolAddress((void**)&H5,    g_H5);
    cudaGetSymbolAddress((void**)&H6,    g_H6);
    cudaGetSymbolAddress((void**)&Wvb,   g_Wvb);
    cudaGetSymbolAddress((void**)&Wv2b,  g_Wv2b);
    cudaGetSymbolAddress((void**)&Wqb,   g_Wqb);
    cudaGetSymbolAddress((void**)&Wkb,   g_Wkb);
    cudaGetSymbolAddress((void**)&Wq2b,  g_Wq2b);
    cudaGetSymbolAddress((void**)&Wk2b,  g_Wk2b);
    cudaGetSymbolAddress((void**)&Win1b, g_Win1b);
    cudaGetSymbolAddress((void**)&Win3b, g_Win3b);
    cudaGetSymbolAddress((void**)&Wout2b,g_Wout2b);
    cudaGetSymbolAddress((void**)&Wout3b,g_Wout3b);
    cudaGetSymbolAddress((void**)&Wtrb,  g_Wtrb);

    const long NC = (long)NN*CC;       // per-batch [n][c]
    const long CN = (long)CC*NN;       // per-batch [c][n]
    const long N2C = (long)NN*2*CC;
    const int total = BB*CC*NN;

    // weights -> bf16
    conv_kernel<<<64, 256>>>(Wv,   Wvb,   CC*CC);
    conv_kernel<<<64, 256>>>(Wv2,  Wv2b,  CC*CC);
    conv_kernel<<<64, 256>>>(Wq,   Wqb,   CC*CC);
    conv_kernel<<<64, 256>>>(Wk,   Wkb,   CC*CC);
    conv_kernel<<<64, 256>>>(Wq2,  Wq2b,  CC*CC);
    conv_kernel<<<64, 256>>>(Wk2,  Wk2b,  CC*CC);
    conv_kernel<<<64, 256>>>(Win1, Win1b, CC*CC);
    conv_kernel<<<64, 256>>>(Win3, Win3b, CC*CC);
    conv_kernel<<<64, 256>>>(Wout2,Wout2b,CC*CC);
    conv_kernel<<<64, 256>>>(Wout3,Wout3b,CC*CC);
    conv_kernel<<<256,256>>>(Wtr,  Wtrb,  2*CC*2*CC);

    dim3 tg(NN/32, CC/32, BB), tb(32, 8);
    convT_kernel<<<tg, tb>>>(x, xT);
    convT_kernel<<<tg, tb>>>(y, yT);
    prep_kernel<<<dim3(8, BB), 256>>>(Wv, z, m, Wfc, bfc, fmzb);

    // yvT[n][c] = yT @ Wv^T
    tc_launch(yT, NC, CC, Wvb, 0, CC, 0, 0, yvT, NC, CC, 1, NN, CC, CC);
    // fmzyT[n][c] = yvT @ (I+fmz)^T
    tc_launch(yvT, NC, CC, fmzb, (long)CC*CC, CC, 0, 0, fmzyT, NC, CC, 1, NN, CC, CC);
    // vb1[c][n] = (I+fmz) @ yv
    tc_launch(fmzb, (long)CC*CC, CC, yvT, NC, CC, 0, 0, vb1, CN, NN, 1, CC, NN, CC);
    // projections (attention-ready layouts)
    tc_launch(xT,    NC, CC, Wqb,  0, CC, bq,  2, qt1, NC, CC, 1, NN, CC, CC);
    tc_launch(fmzyT, NC, CC, Wkb,  0, CC, bk,  2, kt1, NC, CC, 1, NN, CC, CC);
    tc_launch(xT,    NC, CC, Wq2b, 0, CC, bq2, 2, qt2, NC, CC, 1, NN, CC, CC);
    tc_launch(xT,    NC, CC, Wk2b, 0, CC, bk2, 2, kt2, NC, CC, 1, NN, CC, CC);
    tc_launch(Wv2b, 0, CC, xT, NC, CC, 0, 0, vb2, CN, NN, 1, CC, NN, CC);

    // attention (unchanged, validated)
    attn_tc_kernel<<<dim3(NN/QT, BB, 2), 256>>>(qt1, kt1, vb1, gamma,  os1,
                                                qt2, kt2, vb2, gamma2, os2);

    convT_kernel<<<tg, tb>>>(os1, os1T);
    convT_kernel<<<tg, tb>>>(os2, os2T);

    // H1T/H3T -> H13T halves (ld 512)
    tc_launch(os1T, NC, CC, Win1b, 0, CC, bin1, 2, H13T,        N2C, 2*CC, 1, NN, CC, CC);
    tc_launch(os2T, NC, CC, Win3b, 0, CC, bin3, 2, H13T + CC,   N2C, 2*CC, 1, NN, CC, CC);
    // HtraT[n][512] = H13T @ Wtr^T
    tc_launch(H13T, N2C, 2*CC, Wtrb, 0, 2*CC, btr, 2, HtraT, N2C, 2*CC, 1, NN, 2*CC, 2*CC);
    // H5/H6 [c][n] fp32
    tc_launch(Wout2b, 0, CC, HtraT,      N2C, 2*CC, bout2, 1, H5, CN, NN, 0, CC, NN, CC);
    tc_launch(Wout3b, 0, CC, HtraT + CC, N2C, 2*CC, bout3, 1, H6, CN, NN, 0, CC, NN, CC);

    final_kernel<<<1024, 256>>>(x, H5, H6, os1, os2, out, total);
}